// round 9
// baseline (speedup 1.0000x reference)
#include <cuda_runtime.h>
#include <cuda_bf16.h>
#include <cfloat>

#define NN 2048
#define FF 64
#define KTOP 8
#define OUT_ROW ((KTOP + 1) * FF)   // 576

#define NBINS 512
#define BIN_HI 4.25f
#define BIN_W  (8.5f / (float)NBINS)
#define BIN_INVW ((float)NBINS / 8.5f)

#define SSTAGE 512
#define BATCH 8
#define DEPTH 6

// Per-feature candidate lists, descending value-bins (split arrays).
__device__ float g_xval[FF * NN];   // candidate x value
__device__ int   g_off [FF * NN];   // adj row element-offset (n * NN)
__device__ float g_bnd [FF * NN];   // max(bin upper edge, 0): bound on ALL later products

__device__ __forceinline__ int bin_of(float v) {
    int b = (int)((BIN_HI - v) * BIN_INVW);
    return max(0, min(NBINS - 1, b));
}
__device__ __forceinline__ float remaining_bound(float v) {
    int b = bin_of(v);
    return (b == 0) ? FLT_MAX : (BIN_HI - (float)b * BIN_W + 1e-3f);
}

// ---------------------------------------------------------------------------
// Kernel 1: per-feature bucket binning -> split arrays + precomputed bound
// ---------------------------------------------------------------------------
__global__ void __launch_bounds__(1024) bin_cols_kernel(const float* __restrict__ x) {
    __shared__ float sx[NN];
    __shared__ int   cnt[NBINS];
    __shared__ int   sa[NBINS];
    __shared__ int   sb[NBINS];
    __shared__ int   cursor[NBINS];

    const int f   = blockIdx.x;
    const int tid = threadIdx.x;
    const int bs  = blockDim.x;   // 1024

    for (int i = tid; i < NBINS; i += bs) cnt[i] = 0;
    __syncthreads();

    for (int i = tid; i < NN; i += bs) {
        float v = __ldg(&x[i * FF + f]);
        sx[i] = v;
        atomicAdd(&cnt[bin_of(v)], 1);
    }
    __syncthreads();

    for (int i = tid; i < NBINS; i += bs) sa[i] = cnt[i];
    __syncthreads();
    int* src = sa; int* dst = sb;
    for (int d = 1; d < NBINS; d <<= 1) {
        for (int i = tid; i < NBINS; i += bs)
            dst[i] = src[i] + ((i >= d) ? src[i - d] : 0);
        __syncthreads();
        int* t = src; src = dst; dst = t;
    }
    for (int i = tid; i < NBINS; i += bs) cursor[i] = src[i] - cnt[i];
    __syncthreads();

    float* oxv = g_xval + (size_t)f * NN;
    int*   oof = g_off  + (size_t)f * NN;
    float* obd = g_bnd  + (size_t)f * NN;
    for (int i = tid; i < NN; i += bs) {
        float v = sx[i];
        int pos = atomicAdd(&cursor[bin_of(v)], 1);
        oxv[pos] = v;
        oof[pos] = i * NN;
        obd[pos] = fmaxf(remaining_bound(v), 0.0f);
    }
}

// ---------------------------------------------------------------------------
// Kernel 2: pruned top-8 scan, depth-6 rotating prefetch (MLP=48 per warp).
// One warp per (f, 32 consecutive m); 64-thread blocks (2 warps, same f);
// grid 2048 -> 13.8 blocks/SM for fine scheduling granularity.
// ---------------------------------------------------------------------------
__global__ void __launch_bounds__(64, 12) topk_scan_kernel(
        const float* __restrict__ adj,
        const float* __restrict__ x,
        float* __restrict__ out) {
    __shared__ float sxv[SSTAGE];   // 2 KB
    __shared__ int   soff[SSTAGE];  // 2 KB
    __shared__ float sbd[SSTAGE];   // 2 KB

    const int f    = blockIdx.x >> 5;                        // 32 blocks/feature
    const int mg   = (blockIdx.x & 31) * 2 + (threadIdx.x >> 5);
    const int lane = threadIdx.x & 31;
    const int m    = mg * 32 + lane;

    const float* __restrict__ gxv = g_xval + (size_t)f * NN;
    const int*   __restrict__ gof = g_off  + (size_t)f * NN;
    const float* __restrict__ gbd = g_bnd  + (size_t)f * NN;

    for (int i = threadIdx.x; i < SSTAGE; i += 64) {
        sxv[i]  = __ldg(&gxv[i]);
        soff[i] = __ldg(&gof[i]);
        sbd[i]  = __ldg(&gbd[i]);
    }
    __syncthreads();

    const float* __restrict__ acol = adj + m;

    float arr[KTOP];
#pragma unroll
    for (int j = 0; j < KTOP; j++) arr[j] = -FLT_MAX;

    float a0[BATCH], a1[BATCH], a2[BATCH], a3[BATCH], a4[BATCH], a5[BATCH];

#define PREF(AB, b) do {                                                    \
    _Pragma("unroll")                                                       \
    for (int c = 0; c < BATCH; c++)                                         \
        AB[c] = __ldg(acol + soff[(b) + c]);                                \
    } while (0)

#define PROC(AB, b) do {                                                    \
    float v[BATCH];                                                         \
    _Pragma("unroll")                                                       \
    for (int c = 0; c < BATCH; c++) v[c] = AB[c] * sxv[(b) + c];            \
    float m01 = fmaxf(v[0], v[1]), m23 = fmaxf(v[2], v[3]);                 \
    float m45 = fmaxf(v[4], v[5]), m67 = fmaxf(v[6], v[7]);                 \
    float vmax = fmaxf(fmaxf(m01, m23), fmaxf(m45, m67));                   \
    if (__any_sync(0xffffffffu, vmax > arr[KTOP - 1])) {                    \
        _Pragma("unroll")                                                   \
        for (int c = 0; c < BATCH; c++) {                                   \
            if (__any_sync(0xffffffffu, v[c] > arr[KTOP - 1])) {            \
                float keep = v[c];                                          \
                _Pragma("unroll")                                           \
                for (int j = 0; j < KTOP; j++) {                            \
                    float mx = fmaxf(arr[j], keep);                         \
                    keep     = fminf(arr[j], keep);                         \
                    arr[j]   = mx;                                          \
                } } } } } while (0)

#define TERM(b) (!__any_sync(0xffffffffu, sbd[(b) + BATCH - 1] > arr[KTOP - 1]))

    PREF(a0, 0);         PREF(a1, BATCH);     PREF(a2, 2 * BATCH);
    PREF(a3, 3 * BATCH); PREF(a4, 4 * BATCH); PREF(a5, 5 * BATCH);

    int base = 0;
    bool fin = false;

    // Steady state: 6 batches (48 loads) always in flight.
    while (base + 7 * BATCH <= SSTAGE) {
        PROC(a0, base); if (TERM(base)) { fin = true; break; }
        PREF(a0, base + 6 * BATCH); base += BATCH;
        PROC(a1, base); if (TERM(base)) { fin = true; break; }
        PREF(a1, base + 6 * BATCH); base += BATCH;
        PROC(a2, base); if (TERM(base)) { fin = true; break; }
        PREF(a2, base + 6 * BATCH); base += BATCH;
        PROC(a3, base); if (TERM(base)) { fin = true; break; }
        PREF(a3, base + 6 * BATCH); base += BATCH;
        PROC(a4, base); if (TERM(base)) { fin = true; break; }
        PREF(a4, base + 6 * BATCH); base += BATCH;
        PROC(a5, base); if (TERM(base)) { fin = true; break; }
        PREF(a5, base + 6 * BATCH); base += BATCH;
    }

    if (!fin) {   // drain: buffers hold exactly base .. base+47 (= SSTAGE end)
        PROC(a0, base); fin = TERM(base); base += BATCH;
        if (!fin) { PROC(a1, base); fin = TERM(base); base += BATCH; }
        if (!fin) { PROC(a2, base); fin = TERM(base); base += BATCH; }
        if (!fin) { PROC(a3, base); fin = TERM(base); base += BATCH; }
        if (!fin) { PROC(a4, base); fin = TERM(base); base += BATCH; }
        if (!fin) { PROC(a5, base); fin = TERM(base); base += BATCH; }
    }

    // Global fallback (rarely reached; preserves exactness)
    while (!fin && base + BATCH <= NN) {
        float xg[BATCH];
#pragma unroll
        for (int c = 0; c < BATCH; c++) {
            a0[c] = __ldg(acol + __ldg(&gof[base + c]));
            xg[c] = __ldg(&gxv[base + c]);
        }
        float v[BATCH];
#pragma unroll
        for (int c = 0; c < BATCH; c++) v[c] = a0[c] * xg[c];
#pragma unroll
        for (int c = 0; c < BATCH; c++) {
            if (__any_sync(0xffffffffu, v[c] > arr[KTOP - 1])) {
                float keep = v[c];
#pragma unroll
                for (int j = 0; j < KTOP; j++) {
                    float mx = fmaxf(arr[j], keep);
                    keep     = fminf(arr[j], keep);
                    arr[j]   = mx;
                }
            }
        }
        float bd = __ldg(&gbd[base + BATCH - 1]);
        if (!__any_sync(0xffffffffu, bd > arr[KTOP - 1])) fin = true;
        base += BATCH;
    }
#undef PREF
#undef PROC
#undef TERM

    // out[m, 1+j, f]
    float* o = out + (size_t)m * OUT_ROW + FF + f;
#pragma unroll
    for (int j = 0; j < KTOP; j++) o[j * FF] = arr[j];

    // k=0 slice: out[m, 0, f] = x[m, f]
    out[(size_t)m * OUT_ROW + f] = __ldg(&x[m * FF + f]);
}

extern "C" void kernel_launch(void* const* d_in, const int* in_sizes, int n_in,
                              void* d_out, int out_size) {
    const float* x   = (const float*)d_in[0];
    const float* adj = (const float*)d_in[1];
    if (in_sizes[0] == NN * NN) {
        adj = (const float*)d_in[0];
        x   = (const float*)d_in[1];
    }
    float* out = (float*)d_out;

    bin_cols_kernel<<<FF, 1024>>>(x);

    // 64 f * 32 blocks/f = 2048 blocks of 64 threads (2 warps each)
    topk_scan_kernel<<<2048, 64>>>(adj, x, out);
}

// round 10
// speedup vs baseline: 1.2821x; 1.2821x over previous
#include <cuda_runtime.h>
#include <cuda_bf16.h>
#include <cfloat>

#define NN 2048
#define FF 64
#define KTOP 8
#define OUT_ROW ((KTOP + 1) * FF)   // 576

#define NBINS 512
#define BIN_HI 4.25f
#define BIN_W  (8.5f / (float)NBINS)
#define BIN_INVW ((float)NBINS / 8.5f)

#define SSTAGE 512
#define BATCH 8

// Per-feature candidate lists, descending value-bins (split arrays).
__device__ float g_xval[FF * NN];   // candidate x value
__device__ int   g_off [FF * NN];   // adj row element-offset (n * NN)
__device__ float g_bnd [FF * NN];   // max(bin upper edge, 0): bound on ALL later products

__device__ __forceinline__ int bin_of(float v) {
    int b = (int)((BIN_HI - v) * BIN_INVW);
    return max(0, min(NBINS - 1, b));
}
__device__ __forceinline__ float remaining_bound(float v) {
    int b = bin_of(v);
    return (b == 0) ? FLT_MAX : (BIN_HI - (float)b * BIN_W + 1e-3f);
}

// ---------------------------------------------------------------------------
// Kernel 1: per-feature bucket binning -> split arrays + precomputed bound
// ---------------------------------------------------------------------------
__global__ void __launch_bounds__(512) bin_cols_kernel(const float* __restrict__ x) {
    __shared__ float sx[NN];
    __shared__ int   cnt[NBINS];
    __shared__ int   sa[NBINS];
    __shared__ int   sb[NBINS];
    __shared__ int   cursor[NBINS];

    const int f   = blockIdx.x;
    const int tid = threadIdx.x;
    const int bs  = blockDim.x;

    for (int i = tid; i < NBINS; i += bs) cnt[i] = 0;
    __syncthreads();

    for (int i = tid; i < NN; i += bs) {
        float v = __ldg(&x[i * FF + f]);
        sx[i] = v;
        atomicAdd(&cnt[bin_of(v)], 1);
    }
    __syncthreads();

    for (int i = tid; i < NBINS; i += bs) sa[i] = cnt[i];
    __syncthreads();
    int* src = sa; int* dst = sb;
    for (int d = 1; d < NBINS; d <<= 1) {
        for (int i = tid; i < NBINS; i += bs)
            dst[i] = src[i] + ((i >= d) ? src[i - d] : 0);
        __syncthreads();
        int* t = src; src = dst; dst = t;
    }
    for (int i = tid; i < NBINS; i += bs) cursor[i] = src[i] - cnt[i];
    __syncthreads();

    float* oxv = g_xval + (size_t)f * NN;
    int*   oof = g_off  + (size_t)f * NN;
    float* obd = g_bnd  + (size_t)f * NN;
    for (int i = tid; i < NN; i += bs) {
        float v = sx[i];
        int pos = atomicAdd(&cursor[bin_of(v)], 1);
        oxv[pos] = v;
        oof[pos] = i * NN;
        obd[pos] = fmaxf(remaining_bound(v), 0.0f);
    }
}

// ---------------------------------------------------------------------------
// Kernel 2: pruned top-8 scan (R8 champion shape) + adj L2 prewarm.
// One warp per (f, 32 consecutive m); 128-thread blocks share f; grid 1024.
// Depth-4 rotating prefetch = 32 loads in flight per warp.
// ---------------------------------------------------------------------------
__global__ void __launch_bounds__(128, 8) topk_scan_kernel(
        const float* __restrict__ adj,
        const float* __restrict__ x,
        float* __restrict__ out) {
    __shared__ float sxv[SSTAGE];   // 2 KB
    __shared__ int   soff[SSTAGE];  // 2 KB
    __shared__ float sbd[SSTAGE];   // 2 KB

    const int f    = blockIdx.x >> 4;                        // 16 blocks/feature
    const int mg   = (blockIdx.x & 15) * 4 + (threadIdx.x >> 5);
    const int lane = threadIdx.x & 31;
    const int m    = mg * 32 + lane;

    // --- adj L2 prewarm: each block streams its 16 KB contiguous slice ---
    {
        const float4* aw = (const float4*)adj
                         + (size_t)blockIdx.x * 1024 + threadIdx.x;
        float acc = 0.0f;
#pragma unroll
        for (int i = 0; i < 8; i++) {
            float4 w = __ldg(aw + i * 128);
            acc += w.x + w.y + w.z + w.w;
        }
        // adj >= 0 => acc >= 0; branch never taken, keeps loads live
        if (acc < -1.0f) out[0] = acc;
    }

    const float* __restrict__ gxv = g_xval + (size_t)f * NN;
    const int*   __restrict__ gof = g_off  + (size_t)f * NN;
    const float* __restrict__ gbd = g_bnd  + (size_t)f * NN;

    // Vectorized staging: 512 elems x 3 arrays / 128 threads / 4 = 3 float4 each
    {
        const float4* s1 = (const float4*)gxv;
        const float4* s2 = (const float4*)gof;   // int payload, bit-copied
        const float4* s3 = (const float4*)gbd;
        float4* d1 = (float4*)sxv;
        float4* d2 = (float4*)soff;
        float4* d3 = (float4*)sbd;
        for (int i = threadIdx.x; i < SSTAGE / 4; i += 128) {
            d1[i] = __ldg(s1 + i);
            d2[i] = __ldg(s2 + i);
            d3[i] = __ldg(s3 + i);
        }
    }
    __syncthreads();

    const float* __restrict__ acol = adj + m;

    float arr[KTOP];
#pragma unroll
    for (int j = 0; j < KTOP; j++) arr[j] = -FLT_MAX;

    float a0[BATCH], a1[BATCH], a2[BATCH], a3[BATCH];

#define PREF(AB, b) do {                                                    \
    _Pragma("unroll")                                                       \
    for (int c = 0; c < BATCH; c++)                                         \
        AB[c] = __ldg(acol + soff[(b) + c]);                                \
    } while (0)

// Batch vote; on pass, insert all 8 unconditionally (chain is a no-op for
// values below arr[7]) -- removes 8 serializing votes per inserting batch.
#define PROC(AB, b) do {                                                    \
    float v[BATCH];                                                         \
    _Pragma("unroll")                                                       \
    for (int c = 0; c < BATCH; c++) v[c] = AB[c] * sxv[(b) + c];            \
    float m01 = fmaxf(v[0], v[1]), m23 = fmaxf(v[2], v[3]);                 \
    float m45 = fmaxf(v[4], v[5]), m67 = fmaxf(v[6], v[7]);                 \
    float vmax = fmaxf(fmaxf(m01, m23), fmaxf(m45, m67));                   \
    if (__any_sync(0xffffffffu, vmax > arr[KTOP - 1])) {                    \
        _Pragma("unroll")                                                   \
        for (int c = 0; c < BATCH; c++) {                                   \
            float keep = v[c];                                              \
            _Pragma("unroll")                                               \
            for (int j = 0; j < KTOP; j++) {                                \
                float mx = fmaxf(arr[j], keep);                             \
                keep     = fminf(arr[j], keep);                             \
                arr[j]   = mx;                                              \
            } } } } while (0)

#define TERM(b) (!__any_sync(0xffffffffu, sbd[(b) + BATCH - 1] > arr[KTOP - 1]))

    PREF(a0, 0); PREF(a1, BATCH); PREF(a2, 2 * BATCH); PREF(a3, 3 * BATCH);

    int base = 0;
    bool fin = false;

    // Steady state: 4 batches (32 loads) always in flight.
    while (base + 5 * BATCH <= SSTAGE) {
        PROC(a0, base); if (TERM(base)) { fin = true; break; }
        PREF(a0, base + 4 * BATCH); base += BATCH;
        PROC(a1, base); if (TERM(base)) { fin = true; break; }
        PREF(a1, base + 4 * BATCH); base += BATCH;
        PROC(a2, base); if (TERM(base)) { fin = true; break; }
        PREF(a2, base + 4 * BATCH); base += BATCH;
        PROC(a3, base); if (TERM(base)) { fin = true; break; }
        PREF(a3, base + 4 * BATCH); base += BATCH;
    }

    if (!fin) {   // drain: buffers hold base .. base+31 (exactly to SSTAGE)
        PROC(a0, base); fin = TERM(base); base += BATCH;
        if (!fin) { PROC(a1, base); fin = TERM(base); base += BATCH; }
        if (!fin) { PROC(a2, base); fin = TERM(base); base += BATCH; }
        if (!fin) { PROC(a3, base); fin = TERM(base); base += BATCH; }
    }

    // Global fallback (rarely reached; preserves exactness)
    while (!fin && base + BATCH <= NN) {
        float xg[BATCH];
#pragma unroll
        for (int c = 0; c < BATCH; c++) {
            a0[c] = __ldg(acol + __ldg(&gof[base + c]));
            xg[c] = __ldg(&gxv[base + c]);
        }
#pragma unroll
        for (int c = 0; c < BATCH; c++) {
            float v = a0[c] * xg[c];
            if (__any_sync(0xffffffffu, v > arr[KTOP - 1])) {
                float keep = v;
#pragma unroll
                for (int j = 0; j < KTOP; j++) {
                    float mx = fmaxf(arr[j], keep);
                    keep     = fminf(arr[j], keep);
                    arr[j]   = mx;
                }
            }
        }
        float bd = __ldg(&gbd[base + BATCH - 1]);
        if (!__any_sync(0xffffffffu, bd > arr[KTOP - 1])) fin = true;
        base += BATCH;
    }
#undef PREF
#undef PROC
#undef TERM

    // out[m, 1+j, f]
    float* o = out + (size_t)m * OUT_ROW + FF + f;
#pragma unroll
    for (int j = 0; j < KTOP; j++) o[j * FF] = arr[j];

    // k=0 slice: out[m, 0, f] = x[m, f]
    out[(size_t)m * OUT_ROW + f] = __ldg(&x[m * FF + f]);
}

extern "C" void kernel_launch(void* const* d_in, const int* in_sizes, int n_in,
                              void* d_out, int out_size) {
    const float* x   = (const float*)d_in[0];
    const float* adj = (const float*)d_in[1];
    if (in_sizes[0] == NN * NN) {
        adj = (const float*)d_in[0];
        x   = (const float*)d_in[1];
    }
    float* out = (float*)d_out;

    bin_cols_kernel<<<FF, 512>>>(x);

    // 64 f * 16 blocks/f = 1024 blocks of 128 threads (4 warps each)
    topk_scan_kernel<<<1024, 128>>>(adj, x, out);
}